// round 1
// baseline (speedup 1.0000x reference)
#include <cuda_runtime.h>
#include <cstdint>

#define Nn 2048
#define Bb 64
#define Tt 128
#define Ii 4
#define NSENS 256
#define NOUT 128
#define Oo 2
#define KMICRO 4
#define NBLK 128
#define NT 16        // neurons per block
#define NTHREADS 256
#define KC 128       // k-chunk staged in smem

// persistent state (scratch): h double buffer in [neuron][batch] layout
__device__ float g_h[2][Nn * Bb];
__device__ unsigned g_count;
__device__ volatile unsigned g_gen;

__global__ void hx_init_kernel() {
    int i = blockIdx.x * blockDim.x + threadIdx.x;
    if (i == 0) { g_count = 0u; g_gen = 0u; }
    int stride = gridDim.x * blockDim.x;
    for (int j = i; j < Nn * Bb; j += stride) {
        g_h[0][j] = 0.0f;
        g_h[1][j] = 0.0f;
    }
}

__device__ __forceinline__ void grid_barrier(unsigned step) {
    __syncthreads();
    if (threadIdx.x == 0) {
        unsigned a = atomicAdd(&g_count, 1u);
        if (a == (unsigned)(gridDim.x - 1)) {
            g_count = 0u;
            __threadfence();
            g_gen = step;
        } else {
            while (g_gen < step) { }
            __threadfence();
        }
    }
    __syncthreads();
}

__global__ void __launch_bounds__(NTHREADS, 1) hx_rnn_kernel(
    const float* __restrict__ inputs,   // [B, T, I]
    const float* __restrict__ W,        // [N, N]  (W_rec; out[b,n]=sum_k h[b,k]*W[n,k])
    const float* __restrict__ W_in,     // [NSENS, I]
    const float* __restrict__ b_in,     // [NSENS]
    const float* __restrict__ W_out,    // [O, NOUT]
    const float* __restrict__ b_out,    // [O]
    const void*  sens_idx_p,            // [NSENS] int32 or int64
    const void*  out_idx_p,             // [NOUT] int32 or int64
    float* __restrict__ out)            // [B, T, O]
{
    __shared__ float sh[KC * Bb];       // 32KB h chunk: sh[k][b]
    __shared__ int s_map[NT];           // neuron -> sensory slot (or -1)
    __shared__ int s_out_idx[NOUT];
    __shared__ float s_wout[Oo * NOUT];
    __shared__ int s_flags;

    const int tid = threadIdx.x;
    const int blk = blockIdx.x;
    const int n0 = blk * NT;

    // ---- dtype detection for index arrays (int64 vs int32) ----
    if (tid == 0) {
        const int* ws = (const int*)sens_idx_p;
        int s64 = 1;
        for (int i = 1; i < NSENS; i += 2) { if (ws[i] != 0) { s64 = 0; break; } }
        const int* wo = (const int*)out_idx_p;
        int o64 = 1;
        for (int i = 1; i < NOUT; i += 2) { if (wo[i] != 0) { o64 = 0; break; } }
        s_flags = s64 | (o64 << 1);
    }
    if (tid < NT) s_map[tid] = -1;
    __syncthreads();
    const bool s64 = (s_flags & 1) != 0;
    const bool o64 = (s_flags & 2) != 0;

    // ---- build per-block sensory map ----
    for (int s = tid; s < NSENS; s += NTHREADS) {
        int idx = s64 ? (int)((const long long*)sens_idx_p)[s]
                      : ((const int*)sens_idx_p)[s];
        if (idx >= n0 && idx < n0 + NT) s_map[idx - n0] = s;
    }
    if (blk == 0) {
        for (int j = tid; j < NOUT; j += NTHREADS)
            s_out_idx[j] = o64 ? (int)((const long long*)out_idx_p)[j]
                               : ((const int*)out_idx_p)[j];
        for (int j = tid; j < Oo * NOUT; j += NTHREADS) s_wout[j] = W_out[j];
    }
    __syncthreads();

    // ---- thread -> (neuron, batch quad) mapping ----
    // warp covers 8 neurons x 16 batches => low smem crossbar pressure
    const int w  = tid >> 5;
    const int l  = tid & 31;
    const int gn = w & 1;          // 2 neuron groups of 8
    const int gb = w >> 1;         // 4 batch groups of 16
    const int nin   = l >> 2;      // 0..7
    const int bgin  = l & 3;       // 0..3
    const int nloc  = gn * 8 + nin;          // 0..15
    const int n     = n0 + nloc;
    const int bbase = gb * 16 + bgin * 4;    // 4 consecutive batches
    const float* Wrow = W + (size_t)n * Nn;

    const unsigned sbase = (unsigned)__cvta_generic_to_shared(sh);
    const int s_slot = s_map[nloc];
    const float* wi = (s_slot >= 0) ? (W_in + s_slot * Ii) : W_in;
    const float bi  = (s_slot >= 0) ? b_in[s_slot] : 0.0f;

    unsigned step = 1;
    int p = 0;

    for (int t = 0; t < Tt; ++t) {
        for (int mi = 0; mi < KMICRO; ++mi) {
            const float* cur = g_h[p];
            float* nxt = g_h[p ^ 1];

            unsigned long long a01 = 0ull, a23 = 0ull;  // f32x2 accumulators (=0.f,0.f)

            for (int kc = 0; kc < Nn; kc += KC) {
                __syncthreads();
                // stage h chunk [KC][Bb] -> smem (L2-coherent loads)
                const float4* src = (const float4*)(cur + kc * Bb);
                float4* dst4 = (float4*)sh;
                #pragma unroll
                for (int i = 0; i < (KC * Bb / 4) / NTHREADS; ++i)
                    dst4[tid + i * NTHREADS] = __ldcg(src + tid + i * NTHREADS);
                __syncthreads();

                const float* wrow_kc = Wrow + kc;
                #pragma unroll 4
                for (int kk = 0; kk < KC; kk += 4) {
                    float4 wv = __ldg((const float4*)(wrow_kc + kk));
                    #pragma unroll
                    for (int j = 0; j < 4; ++j) {
                        float wj = (j == 0) ? wv.x : (j == 1) ? wv.y
                                 : (j == 2) ? wv.z : wv.w;
                        unsigned addr = sbase + (unsigned)((((kk + j) * Bb) + bbase) * 4);
                        unsigned long long h01, h23, wp;
                        asm volatile("ld.shared.v2.b64 {%0, %1}, [%2];"
                                     : "=l"(h01), "=l"(h23) : "r"(addr));
                        asm("mov.b64 %0, {%1, %2};" : "=l"(wp) : "f"(wj), "f"(wj));
                        asm("fma.rn.f32x2 %0, %1, %2, %3;"
                            : "=l"(a01) : "l"(h01), "l"(wp), "l"(a01));
                        asm("fma.rn.f32x2 %0, %1, %2, %3;"
                            : "=l"(a23) : "l"(h23), "l"(wp), "l"(a23));
                    }
                }
            }

            float v0, v1, v2, v3;
            asm("mov.b64 {%0, %1}, %2;" : "=f"(v0), "=f"(v1) : "l"(a01));
            asm("mov.b64 {%0, %1}, %2;" : "=f"(v2), "=f"(v3) : "l"(a23));

            if (mi == 0 && s_slot >= 0) {
                // injection = x_t @ W_in^T + b_in at this sensory neuron
                const float w0 = wi[0], w1 = wi[1], w2 = wi[2], w3 = wi[3];
                const float* x0 = inputs + (size_t)(bbase + 0) * (Tt * Ii) + t * Ii;
                const float* x1 = inputs + (size_t)(bbase + 1) * (Tt * Ii) + t * Ii;
                const float* x2 = inputs + (size_t)(bbase + 2) * (Tt * Ii) + t * Ii;
                const float* x3 = inputs + (size_t)(bbase + 3) * (Tt * Ii) + t * Ii;
                v0 += bi + x0[0]*w0 + x0[1]*w1 + x0[2]*w2 + x0[3]*w3;
                v1 += bi + x1[0]*w0 + x1[1]*w1 + x1[2]*w2 + x1[3]*w3;
                v2 += bi + x2[0]*w0 + x2[1]*w1 + x2[2]*w2 + x2[3]*w3;
                v3 += bi + x3[0]*w0 + x3[1]*w1 + x3[2]*w2 + x3[3]*w3;
            }

            float4 ov = make_float4(fmaxf(v0, 0.0f), fmaxf(v1, 0.0f),
                                    fmaxf(v2, 0.0f), fmaxf(v3, 0.0f));
            __stcg((float4*)(nxt + n * Bb + bbase), ov);

            __threadfence();           // release h writes to L2
            grid_barrier(step++);      // global sync
            p ^= 1;
        }

        // ---- readout for timestep t (block 0 only; races argued safe:
        // g_h[p] is not overwritten until after the next barrier, which
        // requires block 0's arrival, which happens after this finishes) ----
        if (blk == 0 && tid < Oo * Bb) {
            const float* hf = g_h[p];
            int o = tid >> 6;
            int b = tid & 63;
            float acc = b_out[o];
            const float* wrow = s_wout + o * NOUT;
            #pragma unroll 4
            for (int j = 0; j < NOUT; ++j)
                acc += wrow[j] * __ldcg(hf + (size_t)s_out_idx[j] * Bb + b);
            out[(size_t)b * (Tt * Oo) + t * Oo + o] = acc;
        }
    }
}

extern "C" void kernel_launch(void* const* d_in, const int* in_sizes, int n_in,
                              void* d_out, int out_size) {
    (void)in_sizes; (void)n_in; (void)out_size;
    const float* inputs = (const float*)d_in[0];
    const float* W_rec  = (const float*)d_in[1];
    const float* W_in   = (const float*)d_in[2];
    const float* b_in   = (const float*)d_in[3];
    const float* W_out  = (const float*)d_in[4];
    const float* b_out  = (const float*)d_in[5];
    const void*  s_idx  = d_in[6];
    const void*  o_idx  = d_in[7];

    hx_init_kernel<<<128, 256>>>();
    hx_rnn_kernel<<<NBLK, NTHREADS>>>(inputs, W_rec, W_in, b_in, W_out, b_out,
                                      s_idx, o_idx, (float*)d_out);
}